// round 1
// baseline (speedup 1.0000x reference)
#include <cuda_runtime.h>
#include <math.h>

// Problem constants
#define NH   8
#define DK   32
#define TLEN 2048
#define NB   4
#define DM   256
#define ROWS (NB * TLEN)   // 8192

// Scratch (allocation-free rule: __device__ globals)
__device__ float g_Q[ROWS * DM];
__device__ float g_K[ROWS * DM];
__device__ float g_V[ROWS * DM];
__device__ float g_O[ROWS * DM];
__device__ float g_inv[NH * NB * TLEN];   // reciprocal softmax rowsums

// ---------------- packed fp32x2 helpers (Blackwell FFMA2) ----------------
__device__ __forceinline__ unsigned long long pk2(float lo, float hi) {
    unsigned long long r;
    asm("mov.b64 %0, {%1, %2};" : "=l"(r) : "f"(lo), "f"(hi));
    return r;
}
__device__ __forceinline__ void ffma2(unsigned long long& d,
                                      unsigned long long a,
                                      unsigned long long b) {
    asm("fma.rn.f32x2 %0, %1, %2, %0;" : "+l"(d) : "l"(a), "l"(b));
}
__device__ __forceinline__ float2 unpk2(unsigned long long v) {
    float2 r;
    asm("mov.b64 {%0, %1}, %2;" : "=f"(r.x), "=f"(r.y) : "l"(v));
    return r;
}
__device__ __forceinline__ float fast_exp2(float x) {
    float y;
    asm("ex2.approx.f32 %0, %1;" : "=f"(y) : "f"(x));
    return y;
}

// ---------------- Kernel 1/4: SGEMM C[M,256] = A[M,256] @ B[256,256] ----------------
// 64x64 tile, BK=32, 256 threads, 4x4 per thread (row-paired f32x2 accumulators)
__global__ __launch_bounds__(256) void sgemm64(const float* __restrict__ A,
                                               const float* __restrict__ B,
                                               float* __restrict__ C) {
    __shared__ float AsT[32][64];  // [k][m] (transposed so m-pairs are contiguous)
    __shared__ float Bs[32][64];   // [k][n]

    const int bm = blockIdx.x * 64;
    const int bn = blockIdx.y * 64;
    const int tid = threadIdx.x;
    const int tx = tid & 15;       // n direction
    const int ty = tid >> 4;       // m direction
    const int m0 = ty * 4;
    const int n0 = tx * 4;

    unsigned long long acc[2][4];  // [m-pair][n]
#pragma unroll
    for (int i = 0; i < 2; i++)
#pragma unroll
        for (int j = 0; j < 4; j++) acc[i][j] = 0ull;

    for (int kb = 0; kb < 256; kb += 32) {
        __syncthreads();
        {
            const int r  = tid >> 3;          // 0..31
            const int c4 = (tid & 7) * 4;     // 0..28
#pragma unroll
            for (int rr = 0; rr < 64; rr += 32) {
                float4 v = *(const float4*)&A[(size_t)(bm + r + rr) * 256 + kb + c4];
                AsT[c4 + 0][r + rr] = v.x;
                AsT[c4 + 1][r + rr] = v.y;
                AsT[c4 + 2][r + rr] = v.z;
                AsT[c4 + 3][r + rr] = v.w;
            }
            const int rb = tid >> 4;          // 0..15
            const int cb = (tid & 15) * 4;
#pragma unroll
            for (int rr = 0; rr < 32; rr += 16) {
                float4 v = *(const float4*)&B[(size_t)(kb + rb + rr) * 256 + bn + cb];
                *(float4*)&Bs[rb + rr][cb] = v;
            }
        }
        __syncthreads();

#pragma unroll
        for (int k = 0; k < 32; k++) {
            float2 a01 = *(float2*)&AsT[k][m0];
            float2 a23 = *(float2*)&AsT[k][m0 + 2];
            unsigned long long A01 = pk2(a01.x, a01.y);
            unsigned long long A23 = pk2(a23.x, a23.y);
            float4 b = *(float4*)&Bs[k][n0];
            unsigned long long B0 = pk2(b.x, b.x);
            unsigned long long B1 = pk2(b.y, b.y);
            unsigned long long B2 = pk2(b.z, b.z);
            unsigned long long B3 = pk2(b.w, b.w);
            ffma2(acc[0][0], A01, B0); ffma2(acc[1][0], A23, B0);
            ffma2(acc[0][1], A01, B1); ffma2(acc[1][1], A23, B1);
            ffma2(acc[0][2], A01, B2); ffma2(acc[1][2], A23, B2);
            ffma2(acc[0][3], A01, B3); ffma2(acc[1][3], A23, B3);
        }
    }

#pragma unroll
    for (int mp = 0; mp < 2; mp++) {
#pragma unroll
        for (int j = 0; j < 4; j++) {
            float2 v = unpk2(acc[mp][j]);
            C[(size_t)(bm + m0 + 2 * mp) * 256 + bn + n0 + j]     = v.x;
            C[(size_t)(bm + m0 + 2 * mp + 1) * 256 + bn + n0 + j] = v.y;
        }
    }
}

// ---------------- Kernel 2: fused QK^T -> exp -> (scores write, rowsum, PV) ----------
// One CTA per (head h, batch n, 64 q-rows). Writes UNNORMALIZED exp-scores to gmem,
// accumulates rowsum and O = P@V in-CTA; O written normalized; 1/rowsum saved for
// the scores scale pass.
__global__ __launch_bounds__(256) void attn_kernel(float* __restrict__ scores) {
    __shared__ float Qs[64][32];
    __shared__ float KsT[32][64];   // [k][col]
    __shared__ float Vs[64][32];
    __shared__ float Ps[64][65];    // padded: PV reads columns
    __shared__ float rs_s[64];

    const int qb = blockIdx.x;   // 0..31
    const int n  = blockIdx.y;   // 0..3
    const int h  = blockIdx.z;   // 0..7
    const int tid = threadIdx.x;
    const int tx = tid & 15;
    const int ty = tid >> 4;
    const int r0 = ty * 4;
    const int c0 = tx * 4;

    const float* Qg = g_Q + ((size_t)(n * TLEN + qb * 64)) * DM + h * DK;
    const float* Kg = g_K + ((size_t)n * TLEN) * DM + h * DK;
    const float* Vg = g_V + ((size_t)n * TLEN) * DM + h * DK;
    float* srow = scores + ((size_t)((h * NB + n) * TLEN + qb * 64)) * TLEN;

    // load Q tile once
    {
        const int r  = tid >> 3;
        const int c4 = (tid & 7) * 4;
#pragma unroll
        for (int rr = 0; rr < 64; rr += 32) {
            float4 v = *(const float4*)&Qg[(size_t)(r + rr) * DM + c4];
            *(float4*)&Qs[r + rr][c4] = v;
        }
    }
    if (tid < 64) rs_s[tid] = 0.0f;

    // O accumulators: thread covers rows (rO, rO+1) x dv cols d0..d0+3
    const int rO = (tid >> 3) * 2;
    const int d0 = (tid & 7) * 4;
    unsigned long long oacc[2][2] = {0ull, 0ull, 0ull, 0ull};
    float rsum[4] = {0.f, 0.f, 0.f, 0.f};

    const float sc = 0.25503480f;  // log2(e)/sqrt(32)

    for (int kb = 0; kb < TLEN; kb += 64) {
        __syncthreads();
        {
            const int r  = tid >> 3;
            const int c4 = (tid & 7) * 4;
#pragma unroll
            for (int rr = 0; rr < 64; rr += 32) {
                float4 kv = *(const float4*)&Kg[(size_t)(kb + r + rr) * DM + c4];
                KsT[c4 + 0][r + rr] = kv.x;
                KsT[c4 + 1][r + rr] = kv.y;
                KsT[c4 + 2][r + rr] = kv.z;
                KsT[c4 + 3][r + rr] = kv.w;
                float4 vv = *(const float4*)&Vg[(size_t)(kb + r + rr) * DM + c4];
                *(float4*)&Vs[r + rr][c4] = vv;
            }
        }
        __syncthreads();

        // QK^T: 4 rows x 4 cols per thread, f32x2 paired over columns
        unsigned long long s2[4][2];
#pragma unroll
        for (int i = 0; i < 4; i++) { s2[i][0] = 0ull; s2[i][1] = 0ull; }
#pragma unroll
        for (int k = 0; k < 32; k++) {
            float2 k01 = *(float2*)&KsT[k][c0];
            float2 k23 = *(float2*)&KsT[k][c0 + 2];
            unsigned long long K01 = pk2(k01.x, k01.y);
            unsigned long long K23 = pk2(k23.x, k23.y);
#pragma unroll
            for (int i = 0; i < 4; i++) {
                float q = Qs[r0 + i][k];
                unsigned long long Q2 = pk2(q, q);
                ffma2(s2[i][0], Q2, K01);
                ffma2(s2[i][1], Q2, K23);
            }
        }

        // exp, stage to smem, write unnormalized scores, accumulate rowsum
#pragma unroll
        for (int i = 0; i < 4; i++) {
            float2 p01 = unpk2(s2[i][0]);
            float2 p23 = unpk2(s2[i][1]);
            float p0 = fast_exp2(p01.x * sc);
            float p1 = fast_exp2(p01.y * sc);
            float p2 = fast_exp2(p23.x * sc);
            float p3 = fast_exp2(p23.y * sc);
            rsum[i] += (p0 + p1) + (p2 + p3);
            Ps[r0 + i][c0]     = p0;
            Ps[r0 + i][c0 + 1] = p1;
            Ps[r0 + i][c0 + 2] = p2;
            Ps[r0 + i][c0 + 3] = p3;
            float4 w = make_float4(p0, p1, p2, p3);
            *(float4*)&srow[(size_t)(r0 + i) * TLEN + kb + c0] = w;
        }
        __syncthreads();

        // PV: O[rO..rO+1][d0..d0+3] += P[r][c] * V[c][d]
#pragma unroll 8
        for (int c = 0; c < 64; c++) {
            float p0 = Ps[rO][c];
            float p1 = Ps[rO + 1][c];
            float2 v01 = *(float2*)&Vs[c][d0];
            float2 v23 = *(float2*)&Vs[c][d0 + 2];
            unsigned long long V01 = pk2(v01.x, v01.y);
            unsigned long long V23 = pk2(v23.x, v23.y);
            unsigned long long P0 = pk2(p0, p0);
            unsigned long long P1 = pk2(p1, p1);
            ffma2(oacc[0][0], P0, V01);
            ffma2(oacc[0][1], P0, V23);
            ffma2(oacc[1][0], P1, V01);
            ffma2(oacc[1][1], P1, V23);
        }
    }

    // reduce rowsums across the 16 column-threads
    __syncthreads();
#pragma unroll
    for (int i = 0; i < 4; i++) atomicAdd(&rs_s[r0 + i], rsum[i]);
    __syncthreads();

    if (tid < 64) {
        g_inv[(size_t)(h * NB + n) * TLEN + qb * 64 + tid] = 1.0f / rs_s[tid];
    }

    // write normalized O in [n, T, h*32 + d] layout (heads pre-concatenated)
    float* Og = g_O + ((size_t)(n * TLEN + qb * 64)) * DM + h * DK;
    const float inv0 = 1.0f / rs_s[rO];
    const float inv1 = 1.0f / rs_s[rO + 1];
    float2 o00 = unpk2(oacc[0][0]);
    float2 o01 = unpk2(oacc[0][1]);
    float2 o10 = unpk2(oacc[1][0]);
    float2 o11 = unpk2(oacc[1][1]);
    float4 w0 = make_float4(o00.x * inv0, o00.y * inv0, o01.x * inv0, o01.y * inv0);
    float4 w1 = make_float4(o10.x * inv1, o10.y * inv1, o11.x * inv1, o11.y * inv1);
    *(float4*)&Og[(size_t)rO * DM + d0]       = w0;
    *(float4*)&Og[(size_t)(rO + 1) * DM + d0] = w1;
}

// ---------------- Kernel 3: normalize scores in place (memory bound) ----------------
__global__ __launch_bounds__(256) void scale_kernel(float* __restrict__ scores) {
    const size_t idx = (size_t)blockIdx.x * blockDim.x + threadIdx.x;  // float4 index
    const size_t total4 = (size_t)NH * NB * TLEN * (TLEN / 4);
    if (idx >= total4) return;
    float4* p = (float4*)scores;
    float4 v = p[idx];
    const size_t row = idx >> 9;  // (idx*4)/2048
    const float inv = __ldg(&g_inv[row]);
    v.x *= inv; v.y *= inv; v.z *= inv; v.w *= inv;
    p[idx] = v;
}

// ---------------- launcher ----------------
extern "C" void kernel_launch(void* const* d_in, const int* in_sizes, int n_in,
                              void* d_out, int out_size) {
    (void)in_sizes; (void)n_in; (void)out_size;
    const float* query = (const float*)d_in[0];
    const float* key   = (const float*)d_in[1];
    const float* Wq    = (const float*)d_in[2];
    const float* Wk    = (const float*)d_in[3];
    const float* Wv    = (const float*)d_in[4];
    const float* Wo    = (const float*)d_in[5];

    float* out    = (float*)d_out;                         // [4, 2048, 256]
    float* scores = (float*)d_out + (size_t)ROWS * DM;     // [8, 4, 2048, 2048]

    float *pQ, *pK, *pV, *pO;
    cudaGetSymbolAddress((void**)&pQ, g_Q);
    cudaGetSymbolAddress((void**)&pK, g_K);
    cudaGetSymbolAddress((void**)&pV, g_V);
    cudaGetSymbolAddress((void**)&pO, g_O);

    dim3 gemmGrid(ROWS / 64, DM / 64);
    sgemm64<<<gemmGrid, 256>>>(query, Wq, pQ);
    sgemm64<<<gemmGrid, 256>>>(query, Wk, pK);   // keys come from QUERY input
    sgemm64<<<gemmGrid, 256>>>(key,   Wv, pV);   // values come from KEY input

    dim3 attnGrid(TLEN / 64, NB, NH);
    attn_kernel<<<attnGrid, 256>>>(scores);

    const size_t total4 = (size_t)NH * NB * TLEN * (TLEN / 4);
    scale_kernel<<<(unsigned)((total4 + 255) / 256), 256>>>(scores);

    sgemm64<<<gemmGrid, 256>>>(pO, Wo, out);
}

// round 3
// speedup vs baseline: 1.6410x; 1.6410x over previous
#include <cuda_runtime.h>
#include <cuda_bf16.h>
#include <cstdint>

// Problem constants
#define NH   8
#define DK   32
#define TLEN 2048
#define NB   4
#define DM   256
#define ROWS (NB * TLEN)   // 8192

// Scratch (allocation-free rule: __device__ globals)
__device__ float g_Q[ROWS * DM];
__device__ float g_K[ROWS * DM];
__device__ float g_V[ROWS * DM];
__device__ float g_O[ROWS * DM];
__device__ float g_inv[NH * NB * TLEN];   // reciprocal softmax rowsums

// ===================== helpers =====================
__device__ __forceinline__ float fast_exp2(float x) {
    float y;
    asm("ex2.approx.f32 %0, %1;" : "=f"(y) : "f"(x));
    return y;
}
// pack two f32 -> bf16x2 (lo in low half), and hi/lo split pair
__device__ __forceinline__ uint32_t packbf2(float lo, float hi) {
    uint32_t d;
    asm("cvt.rn.bf16x2.f32 %0, %1, %2;" : "=r"(d) : "f"(hi), "f"(lo));
    return d;
}
__device__ __forceinline__ void split2(float x0, float x1, uint32_t& h, uint32_t& l) {
    h = packbf2(x0, x1);
    float h0 = __uint_as_float(h << 16);
    float h1 = __uint_as_float(h & 0xFFFF0000u);
    l = packbf2(x0 - h0, x1 - h1);
}
// m16n8k16 bf16 MMA, f32 accum (baseline PTX — works on compute_103)
__device__ __forceinline__ void mma_bf16(float* c, uint32_t a0, uint32_t a1,
                                         uint32_t a2, uint32_t a3,
                                         uint32_t b0, uint32_t b1) {
    asm volatile(
        "mma.sync.aligned.m16n8k16.row.col.f32.bf16.bf16.f32 "
        "{%0,%1,%2,%3}, {%4,%5,%6,%7}, {%8,%9}, {%0,%1,%2,%3};"
        : "+f"(c[0]), "+f"(c[1]), "+f"(c[2]), "+f"(c[3])
        : "r"(a0), "r"(a1), "r"(a2), "r"(a3), "r"(b0), "r"(b1));
}

// ===================== fused attention via warp MMA (HMMA) =====================
// CTA: 256 thr (8 warps), 128 q-rows; loop over 32 tiles of 64 keys.
// Strides chosen for conflict-free fragment LDS:
//   Q/K rows: 20 u32 (80B);  V^T rows: 72 u16 (144B)
#define QSTRIDE 20
#define KSTRIDE 20
#define VSTRIDE 72

__global__ void __launch_bounds__(256, 2) attn_mma(float* __restrict__ scores) {
    __shared__ uint32_t sQh[128 * QSTRIDE];
    __shared__ uint32_t sQl[128 * QSTRIDE];
    __shared__ uint32_t sKh[64 * KSTRIDE];
    __shared__ uint32_t sKl[64 * KSTRIDE];
    __shared__ uint16_t sVh[32 * VSTRIDE];
    __shared__ uint16_t sVl[32 * VSTRIDE];

    const int tid = threadIdx.x;
    const int lane = tid & 31;
    const int wid = tid >> 5;
    const int qr = lane >> 2;      // fragment row group 0..7
    const int lm = lane & 3;       // fragment col group 0..3
    const int m0w = wid * 16;      // warp's q-row base within CTA

    const int qb = blockIdx.x, n = blockIdx.y, h = blockIdx.z;

    const float* Qg = g_Q + ((size_t)(n * TLEN + qb * 128)) * DM + h * DK;
    const float* Kg = g_K + ((size_t)n * TLEN) * DM + h * DK;
    const float* Vg = g_V + ((size_t)n * TLEN) * DM + h * DK;

    // ---- stage Q (once): [128 rows][32 bf16 hi | lo], rows padded to 80B
    {
        const int r = tid >> 1;
        const int c = (tid & 1) * 16;   // element offset
        const float* src = Qg + (size_t)r * DM + c;
        uint32_t hh[8], ll[8];
#pragma unroll
        for (int i = 0; i < 8; i++) split2(src[2 * i], src[2 * i + 1], hh[i], ll[i]);
        uint32_t base = r * QSTRIDE + c / 2;
        *(uint4*)&sQh[base]     = make_uint4(hh[0], hh[1], hh[2], hh[3]);
        *(uint4*)&sQh[base + 4] = make_uint4(hh[4], hh[5], hh[6], hh[7]);
        *(uint4*)&sQl[base]     = make_uint4(ll[0], ll[1], ll[2], ll[3]);
        *(uint4*)&sQl[base + 4] = make_uint4(ll[4], ll[5], ll[6], ll[7]);
    }
    __syncthreads();

    // ---- load Q A-fragments (resident for whole kernel)
    uint32_t aQh[2][4], aQl[2][4];
#pragma unroll
    for (int j = 0; j < 2; j++) {
        uint32_t b0 = (m0w + qr) * QSTRIDE + j * 8 + lm;
        uint32_t b1 = (m0w + qr + 8) * QSTRIDE + j * 8 + lm;
        aQh[j][0] = sQh[b0];     aQh[j][1] = sQh[b1];
        aQh[j][2] = sQh[b0 + 4]; aQh[j][3] = sQh[b1 + 4];
        aQl[j][0] = sQl[b0];     aQl[j][1] = sQl[b1];
        aQl[j][2] = sQl[b0 + 4]; aQl[j][3] = sQl[b1 + 4];
    }

    float O[4][4];
#pragma unroll
    for (int g = 0; g < 4; g++)
#pragma unroll
        for (int i = 0; i < 4; i++) O[g][i] = 0.0f;
    float rs0 = 0.0f, rs1 = 0.0f;

    const float SC = 0.25503480f;  // log2(e)/sqrt(32)
    float* srow0 = scores + ((size_t)((h * NB + n) * TLEN + qb * 128 + m0w + qr)) * TLEN;
    float* srow1 = srow0 + 8 * (size_t)TLEN;

    for (int tile = 0; tile < 32; tile++) {
        const int kb = tile * 64;
        __syncthreads();   // previous tile's reads done before overwrite

        // ---- stage K tile: [64 keys][32 bf16 hi|lo], 80B rows
        {
            const int r = tid >> 2;
            const int c = (tid & 3) * 8;
            const float* src = Kg + (size_t)(kb + r) * DM + c;
            uint32_t hh[4], ll[4];
#pragma unroll
            for (int i = 0; i < 4; i++) split2(src[2 * i], src[2 * i + 1], hh[i], ll[i]);
            uint32_t base = r * KSTRIDE + c / 2;
            *(uint4*)&sKh[base] = make_uint4(hh[0], hh[1], hh[2], hh[3]);
            *(uint4*)&sKl[base] = make_uint4(ll[0], ll[1], ll[2], ll[3]);
        }
        // ---- stage V^T tile: [32 dv][64 keys bf16 hi|lo], 144B rows
        {
            const int key = tid >> 2;
            const int c = (tid & 3) * 8;
            const float* src = Vg + (size_t)(kb + key) * DM + c;
#pragma unroll
            for (int i = 0; i < 8; i++) {
                float x = src[i];
                __nv_bfloat16 hb = __float2bfloat16(x);
                float resid = x - __bfloat162float(hb);
                __nv_bfloat16 lb = __float2bfloat16(resid);
                sVh[(c + i) * VSTRIDE + key] = ((__nv_bfloat16_raw)hb).x;
                sVl[(c + i) * VSTRIDE + key] = ((__nv_bfloat16_raw)lb).x;
            }
        }
        __syncthreads();

        // ---- QK^T: S[16 x 64] per warp, 8 n-frags
        float S[8][4];
#pragma unroll
        for (int f = 0; f < 8; f++) {
#pragma unroll
            for (int i = 0; i < 4; i++) S[f][i] = 0.0f;
#pragma unroll
            for (int j = 0; j < 2; j++) {
                uint32_t kb0 = (f * 8 + qr) * KSTRIDE + j * 8 + lm;
                uint32_t kh0 = sKh[kb0], kh1 = sKh[kb0 + 4];
                uint32_t kl0 = sKl[kb0], kl1 = sKl[kb0 + 4];
                mma_bf16(S[f], aQh[j][0], aQh[j][1], aQh[j][2], aQh[j][3], kh0, kh1);
                mma_bf16(S[f], aQh[j][0], aQh[j][1], aQh[j][2], aQh[j][3], kl0, kl1);
                mma_bf16(S[f], aQl[j][0], aQl[j][1], aQl[j][2], aQl[j][3], kh0, kh1);
            }
        }

        // ---- exp + rowsum + coalesced unnormalized score store
#pragma unroll
        for (int f = 0; f < 8; f++) {
            float p0 = fast_exp2(S[f][0] * SC);
            float p1 = fast_exp2(S[f][1] * SC);
            float p2 = fast_exp2(S[f][2] * SC);
            float p3 = fast_exp2(S[f][3] * SC);
            rs0 += p0 + p1;
            rs1 += p2 + p3;
            S[f][0] = p0; S[f][1] = p1; S[f][2] = p2; S[f][3] = p3;
            const int col = kb + f * 8 + lm * 2;
            *(float2*)(srow0 + col) = make_float2(p0, p1);
            *(float2*)(srow1 + col) = make_float2(p2, p3);
        }

        // ---- PV: P (from S regs, C-frag == A-frag layout) @ V^T
#pragma unroll
        for (int kk = 0; kk < 4; kk++) {
            uint32_t ah[4], al[4];
            split2(S[2 * kk][0],     S[2 * kk][1],     ah[0], al[0]);
            split2(S[2 * kk][2],     S[2 * kk][3],     ah[1], al[1]);
            split2(S[2 * kk + 1][0], S[2 * kk + 1][1], ah[2], al[2]);
            split2(S[2 * kk + 1][2], S[2 * kk + 1][3], ah[3], al[3]);
#pragma unroll
            for (int g = 0; g < 4; g++) {
                uint32_t vb = ((g * 8 + qr) * VSTRIDE) / 2 + kk * 8 + lm;
                uint32_t vh0 = *(const uint32_t*)&sVh[vb * 2];
                uint32_t vh1 = *(const uint32_t*)&sVh[vb * 2 + 8];
                uint32_t vl0 = *(const uint32_t*)&sVl[vb * 2];
                uint32_t vl1 = *(const uint32_t*)&sVl[vb * 2 + 8];
                mma_bf16(O[g], ah[0], ah[1], ah[2], ah[3], vh0, vh1);
                mma_bf16(O[g], ah[0], ah[1], ah[2], ah[3], vl0, vl1);
                mma_bf16(O[g], al[0], al[1], al[2], al[3], vh0, vh1);
            }
        }
    }

    // ---- rowsum reduce across the 4 lanes of each row quad
    rs0 += __shfl_xor_sync(0xFFFFFFFFu, rs0, 1);
    rs0 += __shfl_xor_sync(0xFFFFFFFFu, rs0, 2);
    rs1 += __shfl_xor_sync(0xFFFFFFFFu, rs1, 1);
    rs1 += __shfl_xor_sync(0xFFFFFFFFu, rs1, 2);
    const float inv0 = 1.0f / rs0;
    const float inv1 = 1.0f / rs1;

    const size_t invbase = (size_t)(h * NB + n) * TLEN + qb * 128 + m0w + qr;
    if (lm == 0) {
        g_inv[invbase]     = inv0;
        g_inv[invbase + 8] = inv1;
    }

    // ---- normalized O write: [n, T, h*32 + dv]
    float* Og0 = g_O + ((size_t)(n * TLEN + qb * 128 + m0w + qr)) * DM + h * DK;
    float* Og1 = Og0 + 8 * (size_t)DM;
#pragma unroll
    for (int g = 0; g < 4; g++) {
        const int col = g * 8 + lm * 2;
        *(float2*)(Og0 + col) = make_float2(O[g][0] * inv0, O[g][1] * inv0);
        *(float2*)(Og1 + col) = make_float2(O[g][2] * inv1, O[g][3] * inv1);
    }
}

// ===================== SIMT SGEMM (unchanged, passing) =====================
__device__ __forceinline__ unsigned long long pk2(float lo, float hi) {
    unsigned long long r;
    asm("mov.b64 %0, {%1, %2};" : "=l"(r) : "f"(lo), "f"(hi));
    return r;
}
__device__ __forceinline__ void ffma2(unsigned long long& d, unsigned long long a,
                                      unsigned long long b) {
    asm("fma.rn.f32x2 %0, %1, %2, %0;" : "+l"(d) : "l"(a), "l"(b));
}
__device__ __forceinline__ float2 unpk2(unsigned long long v) {
    float2 r;
    asm("mov.b64 {%0, %1}, %2;" : "=f"(r.x), "=f"(r.y) : "l"(v));
    return r;
}

__global__ __launch_bounds__(256) void sgemm64(const float* __restrict__ A,
                                               const float* __restrict__ B,
                                               float* __restrict__ C) {
    __shared__ float AsT[32][64];
    __shared__ float Bs[32][64];

    const int bm = blockIdx.x * 64;
    const int bn = blockIdx.y * 64;
    const int tid = threadIdx.x;
    const int tx = tid & 15;
    const int ty = tid >> 4;
    const int m0 = ty * 4;
    const int n0 = tx * 4;

    unsigned long long acc[2][4];
#pragma unroll
    for (int i = 0; i < 2; i++)
#pragma unroll
        for (int j = 0; j < 4; j++) acc[i][j] = 0ull;

    for (int kb = 0; kb < 256; kb += 32) {
        __syncthreads();
        {
            const int r  = tid >> 3;
            const int c4 = (tid & 7) * 4;
#pragma unroll
            for (int rr = 0; rr < 64; rr += 32) {
                float4 v = *(const float4*)&A[(size_t)(bm + r + rr) * 256 + kb + c4];
                AsT[c4 + 0][r + rr] = v.x;
                AsT[c4 + 1][r + rr] = v.y;
                AsT[c4 + 2][r + rr] = v.z;
                AsT[c4 + 3][r + rr] = v.w;
            }
            const int rb = tid >> 4;
            const int cb = (tid & 15) * 4;
#pragma unroll
            for (int rr = 0; rr < 32; rr += 16) {
                float4 v = *(const float4*)&B[(size_t)(kb + rb + rr) * 256 + bn + cb];
                *(float4*)&Bs[rb + rr][cb] = v;
            }
        }
        __syncthreads();

#pragma unroll
        for (int k = 0; k < 32; k++) {
            float2 a01 = *(float2*)&AsT[k][m0];
            float2 a23 = *(float2*)&AsT[k][m0 + 2];
            unsigned long long A01 = pk2(a01.x, a01.y);
            unsigned long long A23 = pk2(a23.x, a23.y);
            float4 b = *(float4*)&Bs[k][n0];
            unsigned long long B0 = pk2(b.x, b.x);
            unsigned long long B1 = pk2(b.y, b.y);
            unsigned long long B2 = pk2(b.z, b.z);
            unsigned long long B3 = pk2(b.w, b.w);
            ffma2(acc[0][0], A01, B0); ffma2(acc[1][0], A23, B0);
            ffma2(acc[0][1], A01, B1); ffma2(acc[1][1], A23, B1);
            ffma2(acc[0][2], A01, B2); ffma2(acc[1][2], A23, B2);
            ffma2(acc[0][3], A01, B3); ffma2(acc[1][3], A23, B3);
        }
    }

#pragma unroll
    for (int mp = 0; mp < 2; mp++) {
#pragma unroll
        for (int j = 0; j < 4; j++) {
            float2 v = unpk2(acc[mp][j]);
            C[(size_t)(bm + m0 + 2 * mp) * 256 + bn + n0 + j]     = v.x;
            C[(size_t)(bm + m0 + 2 * mp + 1) * 256 + bn + n0 + j] = v.y;
        }
    }
}

// ===================== scores normalization (memory bound) =====================
__global__ __launch_bounds__(256) void scale_kernel(float* __restrict__ scores) {
    const size_t idx = (size_t)blockIdx.x * blockDim.x + threadIdx.x;
    const size_t total4 = (size_t)NH * NB * TLEN * (TLEN / 4);
    if (idx >= total4) return;
    float4* p = (float4*)scores;
    float4 v = p[idx];
    const size_t row = idx >> 9;
    const float inv = __ldg(&g_inv[row]);
    v.x *= inv; v.y *= inv; v.z *= inv; v.w *= inv;
    p[idx] = v;
}

// ===================== launcher =====================
extern "C" void kernel_launch(void* const* d_in, const int* in_sizes, int n_in,
                              void* d_out, int out_size) {
    (void)in_sizes; (void)n_in; (void)out_size;
    const float* query = (const float*)d_in[0];
    const float* key   = (const float*)d_in[1];
    const float* Wq    = (const float*)d_in[2];
    const float* Wk    = (const float*)d_in[3];
    const float* Wv    = (const float*)d_in[4];
    const float* Wo    = (const float*)d_in[5];

    float* out    = (float*)d_out;                      // [4, 2048, 256]
    float* scores = (float*)d_out + (size_t)ROWS * DM;  // [8, 4, 2048, 2048]

    float *pQ, *pK, *pV, *pO;
    cudaGetSymbolAddress((void**)&pQ, g_Q);
    cudaGetSymbolAddress((void**)&pK, g_K);
    cudaGetSymbolAddress((void**)&pV, g_V);
    cudaGetSymbolAddress((void**)&pO, g_O);

    dim3 gemmGrid(ROWS / 64, DM / 64);
    sgemm64<<<gemmGrid, 256>>>(query, Wq, pQ);
    sgemm64<<<gemmGrid, 256>>>(query, Wk, pK);   // keys come from QUERY input
    sgemm64<<<gemmGrid, 256>>>(key,   Wv, pV);   // values come from KEY input

    dim3 attnGrid(TLEN / 128, NB, NH);           // 16 x 4 x 8 = 512 CTAs
    attn_mma<<<attnGrid, 256>>>(scores);

    const size_t total4 = (size_t)NH * NB * TLEN * (TLEN / 4);
    scale_kernel<<<(unsigned)((total4 + 255) / 256), 256>>>(scores);

    sgemm64<<<gemmGrid, 256>>>(pO, Wo, out);
}

// round 5
// speedup vs baseline: 2.1079x; 1.2845x over previous
#include <cuda_runtime.h>
#include <cuda_bf16.h>
#include <cstdint>

// Problem constants
#define NH   8
#define DK   32
#define TLEN 2048
#define NB   4
#define DM   256
#define ROWS (NB * TLEN)   // 8192

// ---------------- device scratch (allocation-free rule) ----------------
__device__ float    g_inv[NH * NB * TLEN];
// pre-split bf16 hi/lo pairs: [row][128 u32] (u32 = bf16x2 over feature dim)
__device__ uint32_t g_qh[ROWS * 128], g_ql[ROWS * 128];
__device__ uint32_t g_kh[ROWS * 128], g_kl[ROWS * 128];
__device__ uint32_t g_vh[ROWS * 128], g_vl[ROWS * 128];
__device__ float    g_O [ROWS * DM];
// transposed split weights: [4 W][256 n][128 kpair]
__device__ uint32_t g_wth[4 * 256 * 128], g_wtl[4 * 256 * 128];

// ---------------- helpers ----------------
__device__ __forceinline__ float fast_exp2(float x) {
    float y;
    asm("ex2.approx.f32 %0, %1;" : "=f"(y) : "f"(x));
    return y;
}
// pack two f32 -> bf16x2 (x0 in low half)
__device__ __forceinline__ uint32_t packbf2(float x0, float x1) {
    uint32_t d;
    asm("cvt.rn.bf16x2.f32 %0, %1, %2;" : "=r"(d) : "f"(x1), "f"(x0));
    return d;
}
__device__ __forceinline__ void split2(float x0, float x1, uint32_t& h, uint32_t& l) {
    h = packbf2(x0, x1);
    float h0 = __uint_as_float(h << 16);
    float h1 = __uint_as_float(h & 0xFFFF0000u);
    l = packbf2(x0 - h0, x1 - h1);
}
// m16n8k16 bf16 MMA, f32 accum (baseline PTX — valid on compute_103)
__device__ __forceinline__ void mma_bf16(float* c, uint32_t a0, uint32_t a1,
                                         uint32_t a2, uint32_t a3,
                                         uint32_t b0, uint32_t b1) {
    asm volatile(
        "mma.sync.aligned.m16n8k16.row.col.f32.bf16.bf16.f32 "
        "{%0,%1,%2,%3}, {%4,%5,%6,%7}, {%8,%9}, {%0,%1,%2,%3};"
        : "+f"(c[0]), "+f"(c[1]), "+f"(c[2]), "+f"(c[3])
        : "r"(a0), "r"(a1), "r"(a2), "r"(a3), "r"(b0), "r"(b1));
}

// ---------------- prep: W -> transposed split bf16 pairs ----------------
__global__ __launch_bounds__(256) void prep_w(const float* __restrict__ W0,
                                              const float* __restrict__ W1,
                                              const float* __restrict__ W2,
                                              const float* __restrict__ W3) {
    const int idx = blockIdx.x * 256 + threadIdx.x;  // 0 .. 4*32768-1
    const int w = idx >> 15;
    const int r = idx & 32767;
    const int n = r >> 7, kp = r & 127;
    const float* W = (w == 0) ? W0 : (w == 1) ? W1 : (w == 2) ? W2 : W3;
    float x0 = W[(size_t)(2 * kp) * 256 + n];
    float x1 = W[(size_t)(2 * kp + 1) * 256 + n];
    uint32_t h, l;
    split2(x0, x1, h, l);
    g_wth[idx] = h;
    g_wtl[idx] = l;
}

// ---------------- HMMA GEMM: C[8192,256] = A[8192,256] @ W[256,256] ----------------
// 3-term bf16 split (hh + hl + lh). Tile 128M x 64N, k-chunks of 32.
#define GS 20   // row stride in u32 (16 data + 4 pad)
template <bool SPLIT_OUT>
__global__ __launch_bounds__(256, 2) void gemm_tc(const float* __restrict__ A,
                                                  const uint32_t* __restrict__ Bth,
                                                  const uint32_t* __restrict__ Btl,
                                                  uint32_t* __restrict__ outh,
                                                  uint32_t* __restrict__ outl,
                                                  float* __restrict__ outf) {
    __shared__ uint32_t sAh[128 * GS], sAl[128 * GS];
    __shared__ uint32_t sBh[64 * GS],  sBl[64 * GS];

    const int tid = threadIdx.x;
    const int lane = tid & 31;
    const int wid = tid >> 5;
    const int qr = lane >> 2;
    const int lm = lane & 3;
    const int m0w = wid * 16;
    const int bm = blockIdx.x * 128;
    const int bn = blockIdx.y * 64;

    float C[8][4];
#pragma unroll
    for (int f = 0; f < 8; f++)
#pragma unroll
        for (int i = 0; i < 4; i++) C[f][i] = 0.0f;

    for (int kc = 0; kc < 8; kc++) {
        __syncthreads();
#pragma unroll
        for (int t = 0; t < 4; t++) {
            int idx = tid + t * 256;
            int r = idx >> 3, c4 = idx & 7;
            float4 v = *(const float4*)&A[(size_t)(bm + r) * 256 + kc * 32 + c4 * 4];
            uint32_t h0, l0, h1, l1;
            split2(v.x, v.y, h0, l0);
            split2(v.z, v.w, h1, l1);
            sAh[r * GS + c4 * 2]     = h0;
            sAh[r * GS + c4 * 2 + 1] = h1;
            sAl[r * GS + c4 * 2]     = l0;
            sAl[r * GS + c4 * 2 + 1] = l1;
        }
#pragma unroll
        for (int t = 0; t < 4; t++) {
            int idx = tid + t * 256;
            int nn = idx >> 4, c = idx & 15;
            sBh[nn * GS + c] = Bth[(size_t)(bn + nn) * 128 + kc * 16 + c];
            sBl[nn * GS + c] = Btl[(size_t)(bn + nn) * 128 + kc * 16 + c];
        }
        __syncthreads();

#pragma unroll
        for (int j = 0; j < 2; j++) {
            const int ab = (m0w + qr) * GS + j * 8 + lm;
            uint32_t ah0 = sAh[ab],          ah1 = sAh[ab + 8 * GS];
            uint32_t ah2 = sAh[ab + 4],      ah3 = sAh[ab + 8 * GS + 4];
            uint32_t al0 = sAl[ab],          al1 = sAl[ab + 8 * GS];
            uint32_t al2 = sAl[ab + 4],      al3 = sAl[ab + 8 * GS + 4];
#pragma unroll
            for (int f = 0; f < 8; f++) {
                const int bb = (f * 8 + qr) * GS + j * 8 + lm;
                uint32_t bh0 = sBh[bb], bh1 = sBh[bb + 4];
                uint32_t bl0 = sBl[bb], bl1 = sBl[bb + 4];
                mma_bf16(C[f], ah0, ah1, ah2, ah3, bh0, bh1);
                mma_bf16(C[f], ah0, ah1, ah2, ah3, bl0, bl1);
                mma_bf16(C[f], al0, al1, al2, al3, bh0, bh1);
            }
        }
    }

    if (SPLIT_OUT) {
#pragma unroll
        for (int f = 0; f < 8; f++) {
            uint32_t h, l;
            size_t o0 = (size_t)(bm + m0w + qr) * 128 + (bn >> 1) + f * 4 + lm;
            split2(C[f][0], C[f][1], h, l);
            outh[o0] = h; outl[o0] = l;
            split2(C[f][2], C[f][3], h, l);
            outh[o0 + 8 * 128] = h; outl[o0 + 8 * 128] = l;
        }
    } else {
#pragma unroll
        for (int f = 0; f < 8; f++) {
            size_t r0 = (size_t)(bm + m0w + qr) * 256 + bn + f * 8 + lm * 2;
            *(float2*)&outf[r0]           = make_float2(C[f][0], C[f][1]);
            *(float2*)&outf[r0 + 8 * 256] = make_float2(C[f][2], C[f][3]);
        }
    }
}

// ---------------- fused attention (HMMA, pre-split inputs, 3-term PV) ----------------
#define QS 20   // Q/K row stride in u32 (16 data + 4 pad)
#define VS 36   // V^T row stride in u32 (32 data + 4 pad)
#define VG 17   // V staging row stride in u32 (16 data + 1 pad)

__global__ void __launch_bounds__(256, 2) attn_mma(float* __restrict__ scores) {
    __shared__ uint32_t sQh[128 * QS], sQl[128 * QS];   // 20480 B
    __shared__ uint32_t sKh[64 * QS],  sKl[64 * QS];    // 10240 B
    __shared__ uint32_t sVh[32 * VS],  sVl[32 * VS];    //  9216 B
    __shared__ uint32_t vsh[64 * VG],  vsl[64 * VG];    //  8704 B  (total 48640 B)

    const int tid = threadIdx.x;
    const int lane = tid & 31;
    const int wid = tid >> 5;
    const int qr = lane >> 2;
    const int lm = lane & 3;
    const int m0w = wid * 16;

    const int qb = blockIdx.x, n = blockIdx.y, h = blockIdx.z;

    const uint32_t* Qh = g_qh + ((size_t)(n * TLEN + qb * 128)) * 128 + h * 16;
    const uint32_t* Ql = g_ql + ((size_t)(n * TLEN + qb * 128)) * 128 + h * 16;
    const uint32_t* Kh = g_kh + ((size_t)n * TLEN) * 128 + h * 16;
    const uint32_t* Kl = g_kl + ((size_t)n * TLEN) * 128 + h * 16;
    const uint32_t* Vh = g_vh + ((size_t)n * TLEN) * 128 + h * 16;
    const uint32_t* Vl = g_vl + ((size_t)n * TLEN) * 128 + h * 16;

    // ---- stage Q once (pure u32 copy)
#pragma unroll
    for (int t = 0; t < 8; t++) {
        int idx = tid + t * 256;
        int r = idx >> 4, c = idx & 15;
        sQh[r * QS + c] = Qh[(size_t)r * 128 + c];
        sQl[r * QS + c] = Ql[(size_t)r * 128 + c];
    }
    __syncthreads();

    // ---- resident Q fragments
    uint32_t aQh[2][4], aQl[2][4];
#pragma unroll
    for (int j = 0; j < 2; j++) {
        uint32_t b0 = (m0w + qr) * QS + j * 8 + lm;
        uint32_t b1 = (m0w + qr + 8) * QS + j * 8 + lm;
        aQh[j][0] = sQh[b0];     aQh[j][1] = sQh[b1];
        aQh[j][2] = sQh[b0 + 4]; aQh[j][3] = sQh[b1 + 4];
        aQl[j][0] = sQl[b0];     aQl[j][1] = sQl[b1];
        aQl[j][2] = sQl[b0 + 4]; aQl[j][3] = sQl[b1 + 4];
    }

    float O[4][4];
#pragma unroll
    for (int g = 0; g < 4; g++)
#pragma unroll
        for (int i = 0; i < 4; i++) O[g][i] = 0.0f;
    float rs0 = 0.0f, rs1 = 0.0f;

    const float SC = 0.25503480f;  // log2(e)/sqrt(32)
    float* srow0 = scores + ((size_t)((h * NB + n) * TLEN + qb * 128 + m0w + qr)) * TLEN;
    float* srow1 = srow0 + 8 * (size_t)TLEN;

    for (int tile = 0; tile < 32; tile++) {
        const int kb = tile * 64;
        __syncthreads();

        // ---- stage K (hi/lo) + V rows (hi/lo) — pure u32 coalesced copies
#pragma unroll
        for (int t = 0; t < 4; t++) {
            int idx = tid + t * 256;
            int r = idx >> 4, c = idx & 15;
            sKh[r * QS + c] = Kh[(size_t)(kb + r) * 128 + c];
            sKl[r * QS + c] = Kl[(size_t)(kb + r) * 128 + c];
            vsh[r * VG + c] = Vh[(size_t)(kb + r) * 128 + c];
            vsl[r * VG + c] = Vl[(size_t)(kb + r) * 128 + c];
        }
        __syncthreads();

        // ---- QK^T: 3-term split, 48 MMAs
        float S[8][4];
#pragma unroll
        for (int f = 0; f < 8; f++) {
#pragma unroll
            for (int i = 0; i < 4; i++) S[f][i] = 0.0f;
#pragma unroll
            for (int j = 0; j < 2; j++) {
                uint32_t kb0 = (f * 8 + qr) * QS + j * 8 + lm;
                uint32_t kh0 = sKh[kb0], kh1 = sKh[kb0 + 4];
                uint32_t kl0 = sKl[kb0], kl1 = sKl[kb0 + 4];
                mma_bf16(S[f], aQh[j][0], aQh[j][1], aQh[j][2], aQh[j][3], kh0, kh1);
                mma_bf16(S[f], aQh[j][0], aQh[j][1], aQh[j][2], aQh[j][3], kl0, kl1);
                mma_bf16(S[f], aQl[j][0], aQl[j][1], aQl[j][2], aQl[j][3], kh0, kh1);
            }
        }

        // ---- exp + rowsum + coalesced unnormalized score store
#pragma unroll
        for (int f = 0; f < 8; f++) {
            float p0 = fast_exp2(S[f][0] * SC);
            float p1 = fast_exp2(S[f][1] * SC);
            float p2 = fast_exp2(S[f][2] * SC);
            float p3 = fast_exp2(S[f][3] * SC);
            rs0 += p0 + p1;
            rs1 += p2 + p3;
            S[f][0] = p0; S[f][1] = p1; S[f][2] = p2; S[f][3] = p3;
            const int col = kb + f * 8 + lm * 2;
            *(float2*)(srow0 + col) = make_float2(p0, p1);
            *(float2*)(srow1 + col) = make_float2(p2, p3);
        }

        // ---- build V^T hi/lo pairs (u16 transpose from staged rows)
        {
            const uint16_t* vh16 = (const uint16_t*)vsh;
            const uint16_t* vl16 = (const uint16_t*)vsl;
            const int dv = tid & 31;
            const int kp0 = (tid >> 5) * 4;
#pragma unroll
            for (int j = 0; j < 4; j++) {
                const int kp = kp0 + j;
                uint32_t hlo = vh16[(2 * kp) * (2 * VG) + dv];
                uint32_t hhi = vh16[(2 * kp + 1) * (2 * VG) + dv];
                sVh[dv * VS + kp] = hlo | (hhi << 16);
                uint32_t llo = vl16[(2 * kp) * (2 * VG) + dv];
                uint32_t lhi = vl16[(2 * kp + 1) * (2 * VG) + dv];
                sVl[dv * VS + kp] = llo | (lhi << 16);
            }
        }
        __syncthreads();

        // ---- PV: 3-term split (PhVh + PhVl + PlVh), 48 MMAs
#pragma unroll
        for (int kk = 0; kk < 4; kk++) {
            uint32_t ah[4], al[4];
            split2(S[2 * kk][0],     S[2 * kk][1],     ah[0], al[0]);
            split2(S[2 * kk][2],     S[2 * kk][3],     ah[1], al[1]);
            split2(S[2 * kk + 1][0], S[2 * kk + 1][1], ah[2], al[2]);
            split2(S[2 * kk + 1][2], S[2 * kk + 1][3], ah[3], al[3]);
#pragma unroll
            for (int g = 0; g < 4; g++) {
                uint32_t vb = (g * 8 + qr) * VS + kk * 8 + lm;
                uint32_t vh0 = sVh[vb], vh1 = sVh[vb + 4];
                uint32_t vl0 = sVl[vb], vl1 = sVl[vb + 4];
                mma_bf16(O[g], ah[0], ah[1], ah[2], ah[3], vh0, vh1);
                mma_bf16(O[g], ah[0], ah[1], ah[2], ah[3], vl0, vl1);
                mma_bf16(O[g], al[0], al[1], al[2], al[3], vh0, vh1);
            }
        }
    }

    // ---- rowsum reduce across the 4 lanes of each row quad
    rs0 += __shfl_xor_sync(0xFFFFFFFFu, rs0, 1);
    rs0 += __shfl_xor_sync(0xFFFFFFFFu, rs0, 2);
    rs1 += __shfl_xor_sync(0xFFFFFFFFu, rs1, 1);
    rs1 += __shfl_xor_sync(0xFFFFFFFFu, rs1, 2);
    const float inv0 = 1.0f / rs0;
    const float inv1 = 1.0f / rs1;

    const size_t invbase = (size_t)(h * NB + n) * TLEN + qb * 128 + m0w + qr;
    if (lm == 0) {
        g_inv[invbase]     = inv0;
        g_inv[invbase + 8] = inv1;
    }

    // ---- normalized O write (f32): [n, T, h*32 + dv]
    float* Og0 = g_O + ((size_t)(n * TLEN + qb * 128 + m0w + qr)) * DM + h * DK;
    float* Og1 = Og0 + 8 * (size_t)DM;
#pragma unroll
    for (int g = 0; g < 4; g++) {
        const int col = g * 8 + lm * 2;
        *(float2*)(Og0 + col) = make_float2(O[g][0] * inv0, O[g][1] * inv0);
        *(float2*)(Og1 + col) = make_float2(O[g][2] * inv1, O[g][3] * inv1);
    }
}

// ---------------- scores normalization (memory bound) ----------------
__global__ __launch_bounds__(256) void scale_kernel(float* __restrict__ scores) {
    const size_t idx = (size_t)blockIdx.x * blockDim.x + threadIdx.x;
    const size_t total4 = (size_t)NH * NB * TLEN * (TLEN / 4);
    if (idx >= total4) return;
    float4* p = (float4*)scores;
    float4 v = __ldcs(&p[idx]);
    const size_t row = idx >> 9;
    const float inv = __ldg(&g_inv[row]);
    v.x *= inv; v.y *= inv; v.z *= inv; v.w *= inv;
    __stcs(&p[idx], v);
}

// ---------------- launcher ----------------
extern "C" void kernel_launch(void* const* d_in, const int* in_sizes, int n_in,
                              void* d_out, int out_size) {
    (void)in_sizes; (void)n_in; (void)out_size;
    const float* query = (const float*)d_in[0];
    const float* key   = (const float*)d_in[1];
    const float* Wq    = (const float*)d_in[2];
    const float* Wk    = (const float*)d_in[3];
    const float* Wv    = (const float*)d_in[4];
    const float* Wo    = (const float*)d_in[5];

    float* out    = (float*)d_out;                      // [4, 2048, 256]
    float* scores = (float*)d_out + (size_t)ROWS * DM;  // [8, 4, 2048, 2048]

    uint32_t *pqh, *pql, *pkh, *pkl, *pvh, *pvl, *pwth, *pwtl;
    float* pO;
    cudaGetSymbolAddress((void**)&pqh, g_qh);
    cudaGetSymbolAddress((void**)&pql, g_ql);
    cudaGetSymbolAddress((void**)&pkh, g_kh);
    cudaGetSymbolAddress((void**)&pkl, g_kl);
    cudaGetSymbolAddress((void**)&pvh, g_vh);
    cudaGetSymbolAddress((void**)&pvl, g_vl);
    cudaGetSymbolAddress((void**)&pwth, g_wth);
    cudaGetSymbolAddress((void**)&pwtl, g_wtl);
    cudaGetSymbolAddress((void**)&pO, g_O);

    prep_w<<<512, 256>>>(Wq, Wk, Wv, Wo);

    dim3 gg(ROWS / 128, DM / 64);   // (64, 4)
    gemm_tc<true><<<gg, 256>>>(query, pwth,             pwtl,             pqh, pql, nullptr);
    gemm_tc<true><<<gg, 256>>>(query, pwth + 1 * 32768, pwtl + 1 * 32768, pkh, pkl, nullptr);
    gemm_tc<true><<<gg, 256>>>(key,   pwth + 2 * 32768, pwtl + 2 * 32768, pvh, pvl, nullptr);

    dim3 attnGrid(TLEN / 128, NB, NH);   // (16, 4, 8)
    attn_mma<<<attnGrid, 256>>>(scores);

    const size_t total4 = (size_t)NH * NB * TLEN * (TLEN / 4);
    scale_kernel<<<(unsigned)((total4 + 255) / 256), 256>>>(scores);

    gemm_tc<false><<<gg, 256>>>(pO, pwth + 3 * 32768, pwtl + 3 * 32768,
                                nullptr, nullptr, out);
}

// round 6
// speedup vs baseline: 2.5729x; 1.2206x over previous
#include <cuda_runtime.h>
#include <cuda_bf16.h>
#include <cstdint>

// Problem constants
#define NH   8
#define DK   32
#define TLEN 2048
#define NB   4
#define DM   256
#define ROWS (NB * TLEN)   // 8192

// ---------------- device scratch (allocation-free rule) ----------------
// pre-split bf16 hi/lo pairs: [row][128 u32] (u32 = bf16x2 over feature dim)
__device__ uint32_t g_qh[ROWS * 128], g_ql[ROWS * 128];
__device__ uint32_t g_kh[ROWS * 128], g_kl[ROWS * 128];
__device__ uint32_t g_vh[ROWS * 128], g_vl[ROWS * 128];
__device__ float    g_O [ROWS * DM];
// transposed split weights: [4 W][256 n][128 kpair]
__device__ uint32_t g_wth[4 * 256 * 128], g_wtl[4 * 256 * 128];

// ---------------- helpers ----------------
__device__ __forceinline__ float fast_exp2(float x) {
    float y;
    asm("ex2.approx.f32 %0, %1;" : "=f"(y) : "f"(x));
    return y;
}
__device__ __forceinline__ uint32_t packbf2(float x0, float x1) {
    uint32_t d;
    asm("cvt.rn.bf16x2.f32 %0, %1, %2;" : "=r"(d) : "f"(x1), "f"(x0));
    return d;
}
__device__ __forceinline__ void split2(float x0, float x1, uint32_t& h, uint32_t& l) {
    h = packbf2(x0, x1);
    float h0 = __uint_as_float(h << 16);
    float h1 = __uint_as_float(h & 0xFFFF0000u);
    l = packbf2(x0 - h0, x1 - h1);
}
__device__ __forceinline__ void mma_bf16(float* c, uint32_t a0, uint32_t a1,
                                         uint32_t a2, uint32_t a3,
                                         uint32_t b0, uint32_t b1) {
    asm volatile(
        "mma.sync.aligned.m16n8k16.row.col.f32.bf16.bf16.f32 "
        "{%0,%1,%2,%3}, {%4,%5,%6,%7}, {%8,%9}, {%0,%1,%2,%3};"
        : "+f"(c[0]), "+f"(c[1]), "+f"(c[2]), "+f"(c[3])
        : "r"(a0), "r"(a1), "r"(a2), "r"(a3), "r"(b0), "r"(b1));
}
__device__ __forceinline__ uint32_t smem_u32(const void* p) {
    uint32_t a;
    asm("{ .reg .u64 t; cvta.to.shared.u64 t, %1; cvt.u32.u64 %0, t; }" : "=r"(a) : "l"(p));
    return a;
}
__device__ __forceinline__ void cp16(uint32_t daddr, const void* g) {
    asm volatile("cp.async.ca.shared.global [%0], [%1], 16;"
                 :: "r"(daddr), "l"(g) : "memory");
}
#define CP_COMMIT asm volatile("cp.async.commit_group;" ::: "memory")
#define CP_WAIT0  asm volatile("cp.async.wait_group 0;" ::: "memory")

// ---------------- prep: W -> transposed split bf16 pairs ----------------
__global__ __launch_bounds__(256) void prep_w(const float* __restrict__ W0,
                                              const float* __restrict__ W1,
                                              const float* __restrict__ W2,
                                              const float* __restrict__ W3) {
    const int idx = blockIdx.x * 256 + threadIdx.x;
    const int w = idx >> 15;
    const int r = idx & 32767;
    const int n = r >> 7, kp = r & 127;
    const float* W = (w == 0) ? W0 : (w == 1) ? W1 : (w == 2) ? W2 : W3;
    float x0 = W[(size_t)(2 * kp) * 256 + n];
    float x1 = W[(size_t)(2 * kp + 1) * 256 + n];
    uint32_t h, l;
    split2(x0, x1, h, l);
    g_wth[idx] = h;
    g_wtl[idx] = l;
}

// ---------------- HMMA GEMM: C[8192,256] = A[8192,256] @ W[256,256] ----------------
#define GS 20
template <bool SPLIT_OUT>
__global__ __launch_bounds__(256, 2) void gemm_tc(const float* __restrict__ A,
                                                  const uint32_t* __restrict__ Bth,
                                                  const uint32_t* __restrict__ Btl,
                                                  uint32_t* __restrict__ outh,
                                                  uint32_t* __restrict__ outl,
                                                  float* __restrict__ outf) {
    __shared__ uint32_t sAh[128 * GS], sAl[128 * GS];
    __shared__ uint32_t sBh[64 * GS],  sBl[64 * GS];

    const int tid = threadIdx.x;
    const int lane = tid & 31;
    const int wid = tid >> 5;
    const int qr = lane >> 2;
    const int lm = lane & 3;
    const int m0w = wid * 16;
    const int bm = blockIdx.x * 128;
    const int bn = blockIdx.y * 64;

    float C[8][4];
#pragma unroll
    for (int f = 0; f < 8; f++)
#pragma unroll
        for (int i = 0; i < 4; i++) C[f][i] = 0.0f;

    for (int kc = 0; kc < 8; kc++) {
        __syncthreads();
#pragma unroll
        for (int t = 0; t < 4; t++) {
            int idx = tid + t * 256;
            int r = idx >> 3, c4 = idx & 7;
            float4 v = *(const float4*)&A[(size_t)(bm + r) * 256 + kc * 32 + c4 * 4];
            uint32_t h0, l0, h1, l1;
            split2(v.x, v.y, h0, l0);
            split2(v.z, v.w, h1, l1);
            sAh[r * GS + c4 * 2]     = h0;
            sAh[r * GS + c4 * 2 + 1] = h1;
            sAl[r * GS + c4 * 2]     = l0;
            sAl[r * GS + c4 * 2 + 1] = l1;
        }
#pragma unroll
        for (int t = 0; t < 4; t++) {
            int idx = tid + t * 256;
            int nn = idx >> 4, c = idx & 15;
            sBh[nn * GS + c] = Bth[(size_t)(bn + nn) * 128 + kc * 16 + c];
            sBl[nn * GS + c] = Btl[(size_t)(bn + nn) * 128 + kc * 16 + c];
        }
        __syncthreads();

#pragma unroll
        for (int j = 0; j < 2; j++) {
            const int ab = (m0w + qr) * GS + j * 8 + lm;
            uint32_t ah0 = sAh[ab],          ah1 = sAh[ab + 8 * GS];
            uint32_t ah2 = sAh[ab + 4],      ah3 = sAh[ab + 8 * GS + 4];
            uint32_t al0 = sAl[ab],          al1 = sAl[ab + 8 * GS];
            uint32_t al2 = sAl[ab + 4],      al3 = sAl[ab + 8 * GS + 4];
#pragma unroll
            for (int f = 0; f < 8; f++) {
                const int bb = (f * 8 + qr) * GS + j * 8 + lm;
                uint32_t bh0 = sBh[bb], bh1 = sBh[bb + 4];
                uint32_t bl0 = sBl[bb], bl1 = sBl[bb + 4];
                mma_bf16(C[f], ah0, ah1, ah2, ah3, bh0, bh1);
                mma_bf16(C[f], ah0, ah1, ah2, ah3, bl0, bl1);
                mma_bf16(C[f], al0, al1, al2, al3, bh0, bh1);
            }
        }
    }

    if (SPLIT_OUT) {
#pragma unroll
        for (int f = 0; f < 8; f++) {
            uint32_t h, l;
            size_t o0 = (size_t)(bm + m0w + qr) * 128 + (bn >> 1) + f * 4 + lm;
            split2(C[f][0], C[f][1], h, l);
            outh[o0] = h; outl[o0] = l;
            split2(C[f][2], C[f][3], h, l);
            outh[o0 + 8 * 128] = h; outl[o0 + 8 * 128] = l;
        }
    } else {
#pragma unroll
        for (int f = 0; f < 8; f++) {
            size_t r0 = (size_t)(bm + m0w + qr) * 256 + bn + f * 8 + lm * 2;
            *(float2*)&outf[r0]           = make_float2(C[f][0], C[f][1]);
            *(float2*)&outf[r0 + 8 * 256] = make_float2(C[f][2], C[f][3]);
        }
    }
}

// ---------------- fused attention (two-loop, normalized-direct, cp.async DB) ----------------
#define QS 20   // Q/K row stride in u32 (16 data + 4 pad)
#define VG 20   // V staging row stride in u32 (16 data + 4 pad; 16B-aligned rows)
#define VS 36   // V^T row stride in u32 (32 data + 4 pad)

// dynamic smem byte offsets
#define OFF_QH   0                    // 128*QS*4 = 10240
#define OFF_QL   10240                // 10240
#define OFF_K    20480                // 2 bufs * (Kh 5120 + Kl 5120) = 20480
#define OFF_VST  40960                // 2 bufs * (Vh 5120 + Vl 5120) = 20480
#define OFF_VTH  61440                // 32*VS*4 = 4608
#define OFF_VTL  66048                // 4608
#define ATTN_SMEM 70656

__global__ void __launch_bounds__(256, 2) attn_mma(float* __restrict__ scores) {
    extern __shared__ char smem[];
    const uint32_t sb = smem_u32(smem);
    uint32_t* sQh = (uint32_t*)(smem + OFF_QH);
    uint32_t* sQl = (uint32_t*)(smem + OFF_QL);

    const int tid = threadIdx.x;
    const int lane = tid & 31;
    const int wid = tid >> 5;
    const int qr = lane >> 2;
    const int lm = lane & 3;
    const int m0w = wid * 16;

    const int qb = blockIdx.x, n = blockIdx.y, h = blockIdx.z;

    const uint32_t* Qh = g_qh + ((size_t)(n * TLEN + qb * 128)) * 128 + h * 16;
    const uint32_t* Ql = g_ql + ((size_t)(n * TLEN + qb * 128)) * 128 + h * 16;
    const uint32_t* Kh = g_kh + ((size_t)n * TLEN) * 128 + h * 16;
    const uint32_t* Kl = g_kl + ((size_t)n * TLEN) * 128 + h * 16;
    const uint32_t* Vh = g_vh + ((size_t)n * TLEN) * 128 + h * 16;
    const uint32_t* Vl = g_vl + ((size_t)n * TLEN) * 128 + h * 16;

    // per-thread cp.async assignments (2 x 16B per operand pair)
    const int ci  = tid & 255;            // uint4 index 0..255
    const int cw  = tid >> 8;             // unused (tid<256) — keep simple
    (void)cw;
    const int cr  = ci >> 2;              // row 0..63
    const int cc  = (ci & 3) * 4;         // u32 col {0,4,8,12}
    const int chl = 0;                    // each thread does hi then lo

    // K stage: thread covers (cr, cc) for BOTH hi and lo
    auto issueK = [&](int kb, uint32_t bufbase) {
        cp16(bufbase + (cr * QS + cc) * 4,        Kh + (size_t)(kb + cr) * 128 + cc);
        cp16(bufbase + 5120 + (cr * QS + cc) * 4, Kl + (size_t)(kb + cr) * 128 + cc);
    };
    auto issueV = [&](int kb, uint32_t bufbase) {
        cp16(bufbase + (cr * VG + cc) * 4,        Vh + (size_t)(kb + cr) * 128 + cc);
        cp16(bufbase + 5120 + (cr * VG + cc) * 4, Vl + (size_t)(kb + cr) * 128 + cc);
    };
    (void)chl;

    // ---- stage Q once (plain u32 copies)
#pragma unroll
    for (int t = 0; t < 8; t++) {
        int idx = tid + t * 256;
        int r = idx >> 4, c = idx & 15;
        sQh[r * QS + c] = Qh[(size_t)r * 128 + c];
        sQl[r * QS + c] = Ql[(size_t)r * 128 + c];
    }
    // prologue for loop A
    issueK(0, sb + OFF_K);
    CP_COMMIT;
    __syncthreads();

    // ---- resident Q fragments
    uint32_t aQh[2][4], aQl[2][4];
#pragma unroll
    for (int j = 0; j < 2; j++) {
        uint32_t b0 = (m0w + qr) * QS + j * 8 + lm;
        uint32_t b1 = (m0w + qr + 8) * QS + j * 8 + lm;
        aQh[j][0] = sQh[b0];     aQh[j][1] = sQh[b1];
        aQh[j][2] = sQh[b0 + 4]; aQh[j][3] = sQh[b1 + 4];
        aQl[j][0] = sQl[b0];     aQl[j][1] = sQl[b1];
        aQl[j][2] = sQl[b0 + 4]; aQl[j][3] = sQl[b1 + 4];
    }

    const float SC = 0.25503480f;  // log2(e)/sqrt(32)
    float rs0 = 0.0f, rs1 = 0.0f;

    // ================= Loop A: rowsums only =================
    for (int tile = 0; tile < 32; tile++) {
        const int cur = tile & 1;
        CP_WAIT0;
        __syncthreads();
        if (tile + 1 < 32) {
            issueK((tile + 1) * 64, sb + OFF_K + (cur ^ 1) * 10240);
            CP_COMMIT;
        }
        const uint32_t* kh = (const uint32_t*)(smem + OFF_K + cur * 10240);
        const uint32_t* kl = kh + 1280;

        float S[8][4];
#pragma unroll
        for (int f = 0; f < 8; f++) {
#pragma unroll
            for (int i = 0; i < 4; i++) S[f][i] = 0.0f;
#pragma unroll
            for (int j = 0; j < 2; j++) {
                uint32_t kb0 = (f * 8 + qr) * QS + j * 8 + lm;
                uint32_t kh0 = kh[kb0], kh1 = kh[kb0 + 4];
                uint32_t kl0 = kl[kb0], kl1 = kl[kb0 + 4];
                mma_bf16(S[f], aQh[j][0], aQh[j][1], aQh[j][2], aQh[j][3], kh0, kh1);
                mma_bf16(S[f], aQh[j][0], aQh[j][1], aQh[j][2], aQh[j][3], kl0, kl1);
                mma_bf16(S[f], aQl[j][0], aQl[j][1], aQl[j][2], aQl[j][3], kh0, kh1);
            }
        }
#pragma unroll
        for (int f = 0; f < 8; f++) {
            rs0 += fast_exp2(S[f][0] * SC) + fast_exp2(S[f][1] * SC);
            rs1 += fast_exp2(S[f][2] * SC) + fast_exp2(S[f][3] * SC);
        }
    }

    // reduce rowsums across the 4 lanes of each row quad
    rs0 += __shfl_xor_sync(0xFFFFFFFFu, rs0, 1);
    rs0 += __shfl_xor_sync(0xFFFFFFFFu, rs0, 2);
    rs1 += __shfl_xor_sync(0xFFFFFFFFu, rs1, 1);
    rs1 += __shfl_xor_sync(0xFFFFFFFFu, rs1, 2);
    const float li0 = -__log2f(rs0);
    const float li1 = -__log2f(rs1);

    // ================= Loop B: normalized scores + PV =================
    float O[4][4];
#pragma unroll
    for (int g = 0; g < 4; g++)
#pragma unroll
        for (int i = 0; i < 4; i++) O[g][i] = 0.0f;

    float* srow0 = scores + ((size_t)((h * NB + n) * TLEN + qb * 128 + m0w + qr)) * TLEN;
    float* srow1 = srow0 + 8 * (size_t)TLEN;

    uint32_t* sVTh = (uint32_t*)(smem + OFF_VTH);
    uint32_t* sVTl = (uint32_t*)(smem + OFF_VTL);

    __syncthreads();   // loop A fully done before restaging buf0
    issueK(0, sb + OFF_K);
    issueV(0, sb + OFF_VST);
    CP_COMMIT;

    for (int tile = 0; tile < 32; tile++) {
        const int kb = tile * 64;
        const int cur = tile & 1;
        CP_WAIT0;
        __syncthreads();
        if (tile + 1 < 32) {
            issueK((tile + 1) * 64, sb + OFF_K + (cur ^ 1) * 10240);
            issueV((tile + 1) * 64, sb + OFF_VST + (cur ^ 1) * 10240);
            CP_COMMIT;
        }
        const uint32_t* kh = (const uint32_t*)(smem + OFF_K + cur * 10240);
        const uint32_t* kl = kh + 1280;

        // ---- QK^T: 3-term split
        float S[8][4];
#pragma unroll
        for (int f = 0; f < 8; f++) {
#pragma unroll
            for (int i = 0; i < 4; i++) S[f][i] = 0.0f;
#pragma unroll
            for (int j = 0; j < 2; j++) {
                uint32_t kb0 = (f * 8 + qr) * QS + j * 8 + lm;
                uint32_t kh0 = kh[kb0], kh1 = kh[kb0 + 4];
                uint32_t kl0 = kl[kb0], kl1 = kl[kb0 + 4];
                mma_bf16(S[f], aQh[j][0], aQh[j][1], aQh[j][2], aQh[j][3], kh0, kh1);
                mma_bf16(S[f], aQh[j][0], aQh[j][1], aQh[j][2], aQh[j][3], kl0, kl1);
                mma_bf16(S[f], aQl[j][0], aQl[j][1], aQl[j][2], aQl[j][3], kh0, kh1);
            }
        }

        // ---- normalized exp (normalization folded into exponent) + final score store
#pragma unroll
        for (int f = 0; f < 8; f++) {
            float p0 = fast_exp2(fmaf(S[f][0], SC, li0));
            float p1 = fast_exp2(fmaf(S[f][1], SC, li0));
            float p2 = fast_exp2(fmaf(S[f][2], SC, li1));
            float p3 = fast_exp2(fmaf(S[f][3], SC, li1));
            S[f][0] = p0; S[f][1] = p1; S[f][2] = p2; S[f][3] = p3;
            const int col = kb + f * 8 + lm * 2;
            __stcs((float2*)(srow0 + col), make_float2(p0, p1));
            __stcs((float2*)(srow1 + col), make_float2(p2, p3));
        }

        // ---- build V^T hi/lo pairs (u16 transpose from staged rows)
        {
            const uint16_t* vh16 = (const uint16_t*)(smem + OFF_VST + cur * 10240);
            const uint16_t* vl16 = vh16 + 2560;   // 5120 B
            const int dv = tid & 31;
            const int kp0 = (tid >> 5) * 4;
#pragma unroll
            for (int j = 0; j < 4; j++) {
                const int kp = kp0 + j;
                uint32_t hlo = vh16[(2 * kp) * (2 * VG) + dv];
                uint32_t hhi = vh16[(2 * kp + 1) * (2 * VG) + dv];
                sVTh[dv * VS + kp] = hlo | (hhi << 16);
                uint32_t llo = vl16[(2 * kp) * (2 * VG) + dv];
                uint32_t lhi = vl16[(2 * kp + 1) * (2 * VG) + dv];
                sVTl[dv * VS + kp] = llo | (lhi << 16);
            }
        }
        __syncthreads();

        // ---- PV: 3-term split (PhVh + PhVl + PlVh)
#pragma unroll
        for (int kk = 0; kk < 4; kk++) {
            uint32_t ah[4], al[4];
            split2(S[2 * kk][0],     S[2 * kk][1],     ah[0], al[0]);
            split2(S[2 * kk][2],     S[2 * kk][3],     ah[1], al[1]);
            split2(S[2 * kk + 1][0], S[2 * kk + 1][1], ah[2], al[2]);
            split2(S[2 * kk + 1][2], S[2 * kk + 1][3], ah[3], al[3]);
#pragma unroll
            for (int g = 0; g < 4; g++) {
                uint32_t vb = (g * 8 + qr) * VS + kk * 8 + lm;
                uint32_t vh0 = sVTh[vb], vh1 = sVTh[vb + 4];
                uint32_t vl0 = sVTl[vb], vl1 = sVTl[vb + 4];
                mma_bf16(O[g], ah[0], ah[1], ah[2], ah[3], vh0, vh1);
                mma_bf16(O[g], ah[0], ah[1], ah[2], ah[3], vl0, vl1);
                mma_bf16(O[g], al[0], al[1], al[2], al[3], vh0, vh1);
            }
        }
    }

    // ---- O write (already normalized): [n, T, h*32 + dv]
    float* Og0 = g_O + ((size_t)(n * TLEN + qb * 128 + m0w + qr)) * DM + h * DK;
    float* Og1 = Og0 + 8 * (size_t)DM;
#pragma unroll
    for (int g = 0; g < 4; g++) {
        const int col = g * 8 + lm * 2;
        *(float2*)(Og0 + col) = make_float2(O[g][0], O[g][1]);
        *(float2*)(Og1 + col) = make_float2(O[g][2], O[g][3]);
    }
}

// ---------------- launcher ----------------
extern "C" void kernel_launch(void* const* d_in, const int* in_sizes, int n_in,
                              void* d_out, int out_size) {
    (void)in_sizes; (void)n_in; (void)out_size;
    const float* query = (const float*)d_in[0];
    const float* key   = (const float*)d_in[1];
    const float* Wq    = (const float*)d_in[2];
    const float* Wk    = (const float*)d_in[3];
    const float* Wv    = (const float*)d_in[4];
    const float* Wo    = (const float*)d_in[5];

    float* out    = (float*)d_out;                      // [4, 2048, 256]
    float* scores = (float*)d_out + (size_t)ROWS * DM;  // [8, 4, 2048, 2048]

    uint32_t *pqh, *pql, *pkh, *pkl, *pvh, *pvl, *pwth, *pwtl;
    float* pO;
    cudaGetSymbolAddress((void**)&pqh, g_qh);
    cudaGetSymbolAddress((void**)&pql, g_ql);
    cudaGetSymbolAddress((void**)&pkh, g_kh);
    cudaGetSymbolAddress((void**)&pkl, g_kl);
    cudaGetSymbolAddress((void**)&pvh, g_vh);
    cudaGetSymbolAddress((void**)&pvl, g_vl);
    cudaGetSymbolAddress((void**)&pwth, g_wth);
    cudaGetSymbolAddress((void**)&pwtl, g_wtl);
    cudaGetSymbolAddress((void**)&pO, g_O);

    static bool attr_set = false;
    if (!attr_set) {
        cudaFuncSetAttribute(attn_mma, cudaFuncAttributeMaxDynamicSharedMemorySize,
                             ATTN_SMEM);
        attr_set = true;
    }

    prep_w<<<512, 256>>>(Wq, Wk, Wv, Wo);

    dim3 gg(ROWS / 128, DM / 64);   // (64, 4)
    gemm_tc<true><<<gg, 256>>>(query, pwth,             pwtl,             pqh, pql, nullptr);
    gemm_tc<true><<<gg, 256>>>(query, pwth + 1 * 32768, pwtl + 1 * 32768, pkh, pkl, nullptr);
    gemm_tc<true><<<gg, 256>>>(key,   pwth + 2 * 32768, pwtl + 2 * 32768, pvh, pvl, nullptr);

    dim3 attnGrid(TLEN / 128, NB, NH);   // (16, 4, 8)
    attn_mma<<<attnGrid, 256, ATTN_SMEM>>>(scores);

    gemm_tc<false><<<gg, 256>>>(pO, pwth + 3 * 32768, pwtl + 3 * 32768,
                                nullptr, nullptr, out);
}

// round 7
// speedup vs baseline: 3.0471x; 1.1843x over previous
#include <cuda_runtime.h>
#include <cuda_bf16.h>
#include <cstdint>

// Problem constants
#define NH   8
#define DK   32
#define TLEN 2048
#define NB   4
#define DM   256
#define ROWS (NB * TLEN)   // 8192

// ---------------- device scratch (allocation-free rule) ----------------
__device__ uint32_t g_qh[ROWS * 128], g_ql[ROWS * 128];
__device__ uint32_t g_kh[ROWS * 128], g_kl[ROWS * 128];
__device__ uint32_t g_vh[ROWS * 128], g_vl[ROWS * 128];
__device__ float    g_O [ROWS * DM];
// transposed split weights: [4 W][256 n][128 kpair]
__device__ uint32_t g_wth[4 * 256 * 128], g_wtl[4 * 256 * 128];
// pre-transposed V: [n][h][32 dv][1024 keypair u32]
__device__ uint32_t g_vth[NB * NH * 32 * 1024], g_vtl[NB * NH * 32 * 1024];

// ---------------- helpers ----------------
__device__ __forceinline__ float fast_exp2(float x) {
    float y;
    asm("ex2.approx.f32 %0, %1;" : "=f"(y) : "f"(x));
    return y;
}
__device__ __forceinline__ uint32_t packbf2(float x0, float x1) {
    uint32_t d;
    asm("cvt.rn.bf16x2.f32 %0, %1, %2;" : "=r"(d) : "f"(x1), "f"(x0));
    return d;
}
__device__ __forceinline__ void split2(float x0, float x1, uint32_t& h, uint32_t& l) {
    h = packbf2(x0, x1);
    float h0 = __uint_as_float(h << 16);
    float h1 = __uint_as_float(h & 0xFFFF0000u);
    l = packbf2(x0 - h0, x1 - h1);
}
__device__ __forceinline__ void mma_bf16(float* c, uint32_t a0, uint32_t a1,
                                         uint32_t a2, uint32_t a3,
                                         uint32_t b0, uint32_t b1) {
    asm volatile(
        "mma.sync.aligned.m16n8k16.row.col.f32.bf16.bf16.f32 "
        "{%0,%1,%2,%3}, {%4,%5,%6,%7}, {%8,%9}, {%0,%1,%2,%3};"
        : "+f"(c[0]), "+f"(c[1]), "+f"(c[2]), "+f"(c[3])
        : "r"(a0), "r"(a1), "r"(a2), "r"(a3), "r"(b0), "r"(b1));
}
__device__ __forceinline__ uint32_t smem_u32(const void* p) {
    uint32_t a;
    asm("{ .reg .u64 t; cvta.to.shared.u64 t, %1; cvt.u32.u64 %0, t; }" : "=r"(a) : "l"(p));
    return a;
}
__device__ __forceinline__ void cp16(uint32_t daddr, const void* g) {
    asm volatile("cp.async.ca.shared.global [%0], [%1], 16;"
                 :: "r"(daddr), "l"(g) : "memory");
}
#define CP_COMMIT asm volatile("cp.async.commit_group;" ::: "memory")
#define CP_WAIT0  asm volatile("cp.async.wait_group 0;" ::: "memory")

// ---------------- prep: W -> transposed split bf16 pairs ----------------
__global__ __launch_bounds__(256) void prep_w(const float* __restrict__ W0,
                                              const float* __restrict__ W1,
                                              const float* __restrict__ W2,
                                              const float* __restrict__ W3) {
    const int idx = blockIdx.x * 256 + threadIdx.x;
    const int w = idx >> 15;
    const int r = idx & 32767;
    const int n = r >> 7, kp = r & 127;
    const float* W = (w == 0) ? W0 : (w == 1) ? W1 : (w == 2) ? W2 : W3;
    float x0 = W[(size_t)(2 * kp) * 256 + n];
    float x1 = W[(size_t)(2 * kp + 1) * 256 + n];
    uint32_t h, l;
    split2(x0, x1, h, l);
    g_wth[idx] = h;
    g_wtl[idx] = l;
}

// ---------------- HMMA GEMM: C[8192,256] = A[8192,256] @ W[256,256] ----------------
#define GS 20
template <bool SPLIT_OUT>
__global__ __launch_bounds__(256, 2) void gemm_tc(const float* __restrict__ A,
                                                  const uint32_t* __restrict__ Bth,
                                                  const uint32_t* __restrict__ Btl,
                                                  uint32_t* __restrict__ outh,
                                                  uint32_t* __restrict__ outl,
                                                  float* __restrict__ outf) {
    __shared__ uint32_t sAh[128 * GS], sAl[128 * GS];
    __shared__ uint32_t sBh[64 * GS],  sBl[64 * GS];

    const int tid = threadIdx.x;
    const int lane = tid & 31;
    const int wid = tid >> 5;
    const int qr = lane >> 2;
    const int lm = lane & 3;
    const int m0w = wid * 16;
    const int bm = blockIdx.x * 128;
    const int bn = blockIdx.y * 64;

    float C[8][4];
#pragma unroll
    for (int f = 0; f < 8; f++)
#pragma unroll
        for (int i = 0; i < 4; i++) C[f][i] = 0.0f;

    for (int kc = 0; kc < 8; kc++) {
        __syncthreads();
#pragma unroll
        for (int t = 0; t < 4; t++) {
            int idx = tid + t * 256;
            int r = idx >> 3, c4 = idx & 7;
            float4 v = *(const float4*)&A[(size_t)(bm + r) * 256 + kc * 32 + c4 * 4];
            uint32_t h0, l0, h1, l1;
            split2(v.x, v.y, h0, l0);
            split2(v.z, v.w, h1, l1);
            sAh[r * GS + c4 * 2]     = h0;
            sAh[r * GS + c4 * 2 + 1] = h1;
            sAl[r * GS + c4 * 2]     = l0;
            sAl[r * GS + c4 * 2 + 1] = l1;
        }
#pragma unroll
        for (int t = 0; t < 4; t++) {
            int idx = tid + t * 256;
            int nn = idx >> 4, c = idx & 15;
            sBh[nn * GS + c] = Bth[(size_t)(bn + nn) * 128 + kc * 16 + c];
            sBl[nn * GS + c] = Btl[(size_t)(bn + nn) * 128 + kc * 16 + c];
        }
        __syncthreads();

#pragma unroll
        for (int j = 0; j < 2; j++) {
            const int ab = (m0w + qr) * GS + j * 8 + lm;
            uint32_t ah0 = sAh[ab],          ah1 = sAh[ab + 8 * GS];
            uint32_t ah2 = sAh[ab + 4],      ah3 = sAh[ab + 8 * GS + 4];
            uint32_t al0 = sAl[ab],          al1 = sAl[ab + 8 * GS];
            uint32_t al2 = sAl[ab + 4],      al3 = sAl[ab + 8 * GS + 4];
#pragma unroll
            for (int f = 0; f < 8; f++) {
                const int bb = (f * 8 + qr) * GS + j * 8 + lm;
                uint32_t bh0 = sBh[bb], bh1 = sBh[bb + 4];
                uint32_t bl0 = sBl[bb], bl1 = sBl[bb + 4];
                mma_bf16(C[f], ah0, ah1, ah2, ah3, bh0, bh1);
                mma_bf16(C[f], ah0, ah1, ah2, ah3, bl0, bl1);
                mma_bf16(C[f], al0, al1, al2, al3, bh0, bh1);
            }
        }
    }

    if (SPLIT_OUT) {
#pragma unroll
        for (int f = 0; f < 8; f++) {
            uint32_t h, l;
            size_t o0 = (size_t)(bm + m0w + qr) * 128 + (bn >> 1) + f * 4 + lm;
            split2(C[f][0], C[f][1], h, l);
            outh[o0] = h; outl[o0] = l;
            split2(C[f][2], C[f][3], h, l);
            outh[o0 + 8 * 128] = h; outl[o0 + 8 * 128] = l;
        }
    } else {
#pragma unroll
        for (int f = 0; f < 8; f++) {
            size_t r0 = (size_t)(bm + m0w + qr) * 256 + bn + f * 8 + lm * 2;
            *(float2*)&outf[r0]           = make_float2(C[f][0], C[f][1]);
            *(float2*)&outf[r0 + 8 * 256] = make_float2(C[f][2], C[f][3]);
        }
    }
}

// ---------------- V transpose: g_vh/g_vl -> g_vth/g_vtl ----------------
// out[n][h][dv][keypair]: u32 = bf16x2 over (2kp, 2kp+1) keys
__global__ __launch_bounds__(256) void vtrans(void) {
    __shared__ uint32_t sh[64 * 17], sl[64 * 17];
    const int tid = threadIdx.x;
    const int tb = blockIdx.x;   // 64-key tile 0..31
    const int n = blockIdx.y, h = blockIdx.z;

    const uint32_t* Vh = g_vh + ((size_t)n * TLEN + tb * 64) * 128 + h * 16;
    const uint32_t* Vl = g_vl + ((size_t)n * TLEN + tb * 64) * 128 + h * 16;
#pragma unroll
    for (int t = 0; t < 4; t++) {
        int idx = tid + t * 256;
        int r = idx >> 4, c = idx & 15;
        sh[r * 17 + c] = Vh[(size_t)r * 128 + c];
        sl[r * 17 + c] = Vl[(size_t)r * 128 + c];
    }
    __syncthreads();

    const uint16_t* sh16 = (const uint16_t*)sh;
    const uint16_t* sl16 = (const uint16_t*)sl;
    const int kp = tid & 31;
    const int dv0 = (tid >> 5) * 4;
    uint32_t* outh = g_vth + (((size_t)n * NH + h) * 32) * 1024 + tb * 32 + kp;
    uint32_t* outl = g_vtl + (((size_t)n * NH + h) * 32) * 1024 + tb * 32 + kp;
#pragma unroll
    for (int j = 0; j < 4; j++) {
        const int dv = dv0 + j;
        uint32_t a = sh16[(2 * kp) * 34 + dv];
        uint32_t b = sh16[(2 * kp + 1) * 34 + dv];
        outh[(size_t)dv * 1024] = a | (b << 16);
        uint32_t c = sl16[(2 * kp) * 34 + dv];
        uint32_t d = sl16[(2 * kp + 1) * 34 + dv];
        outl[(size_t)dv * 1024] = c | (d << 16);
    }
}

// ---------------- fused attention (two-loop, normalized-direct, cp.async DB) ----------------
#define QS 20   // Q/K row stride in u32 (16 data + 4 pad)
#define VS 36   // V^T row stride in u32 (32 data + 4 pad)

// dynamic smem byte offsets
#define OFF_QH   0                    // 10240
#define OFF_QL   10240                // 10240
#define OFF_K    20480                // 2 bufs x (Kh 5120 + Kl 5120) = 20480
#define OFF_VT   40960                // 2 bufs x (VTh 4608 + VTl 4608) = 18432
#define ATTN_SMEM 59392

__global__ void __launch_bounds__(256, 2) attn_mma(float* __restrict__ scores) {
    extern __shared__ char smem[];
    const uint32_t sb = smem_u32(smem);
    uint32_t* sQh = (uint32_t*)(smem + OFF_QH);
    uint32_t* sQl = (uint32_t*)(smem + OFF_QL);

    const int tid = threadIdx.x;
    const int lane = tid & 31;
    const int wid = tid >> 5;
    const int qr = lane >> 2;
    const int lm = lane & 3;
    const int m0w = wid * 16;

    const int qb = blockIdx.x, n = blockIdx.y, h = blockIdx.z;

    const uint32_t* Qh = g_qh + ((size_t)(n * TLEN + qb * 128)) * 128 + h * 16;
    const uint32_t* Ql = g_ql + ((size_t)(n * TLEN + qb * 128)) * 128 + h * 16;
    const uint32_t* Kh = g_kh + ((size_t)n * TLEN) * 128 + h * 16;
    const uint32_t* Kl = g_kl + ((size_t)n * TLEN) * 128 + h * 16;
    const uint32_t* Vth = g_vth + (((size_t)n * NH + h) * 32) * 1024;
    const uint32_t* Vtl = g_vtl + (((size_t)n * NH + h) * 32) * 1024;

    // K staging assignment: 256 chunks of 16B cover [64 rows][16 u32]
    const int cr = tid >> 2;          // row 0..63
    const int cc = (tid & 3) * 4;     // u32 col {0,4,8,12}
    // V^T staging assignment: 256 chunks cover [32 dv][32 u32]
    const int vr = tid >> 3;          // dv 0..31
    const int vc = (tid & 7) * 4;     // u32 col {0,...,28}

    auto issueKh = [&](int kb, uint32_t bufbase) {
        cp16(bufbase + (cr * QS + cc) * 4, Kh + (size_t)(kb + cr) * 128 + cc);
    };
    auto issueKl = [&](int kb, uint32_t bufbase) {
        cp16(bufbase + 5120 + (cr * QS + cc) * 4, Kl + (size_t)(kb + cr) * 128 + cc);
    };
    auto issueVT = [&](int tile, uint32_t bufbase) {
        cp16(bufbase + (vr * VS + vc) * 4,        Vth + (size_t)vr * 1024 + tile * 32 + vc);
        cp16(bufbase + 4608 + (vr * VS + vc) * 4, Vtl + (size_t)vr * 1024 + tile * 32 + vc);
    };

    // ---- stage Q once
#pragma unroll
    for (int t = 0; t < 8; t++) {
        int idx = tid + t * 256;
        int r = idx >> 4, c = idx & 15;
        sQh[r * QS + c] = Qh[(size_t)r * 128 + c];
        sQl[r * QS + c] = Ql[(size_t)r * 128 + c];
    }
    issueKh(0, sb + OFF_K);
    CP_COMMIT;
    __syncthreads();

    // ---- resident Q fragments
    uint32_t aQh[2][4], aQl[2][4];
#pragma unroll
    for (int j = 0; j < 2; j++) {
        uint32_t b0 = (m0w + qr) * QS + j * 8 + lm;
        uint32_t b1 = (m0w + qr + 8) * QS + j * 8 + lm;
        aQh[j][0] = sQh[b0];     aQh[j][1] = sQh[b1];
        aQh[j][2] = sQh[b0 + 4]; aQh[j][3] = sQh[b1 + 4];
        aQl[j][0] = sQl[b0];     aQl[j][1] = sQl[b1];
        aQl[j][2] = sQl[b0 + 4]; aQl[j][3] = sQl[b1 + 4];
    }

    const float SC = 0.25503480f;  // log2(e)/sqrt(32)
    float rs0 = 0.0f, rs1 = 0.0f;

    // ================= Loop A: rowsums only (hi-only QK) =================
    for (int tile = 0; tile < 32; tile++) {
        const int cur = tile & 1;
        CP_WAIT0;
        __syncthreads();
        if (tile + 1 < 32) {
            issueKh((tile + 1) * 64, sb + OFF_K + (cur ^ 1) * 10240);
            CP_COMMIT;
        }
        const uint32_t* kh = (const uint32_t*)(smem + OFF_K + cur * 10240);

        float S[8][4];
#pragma unroll
        for (int f = 0; f < 8; f++) {
#pragma unroll
            for (int i = 0; i < 4; i++) S[f][i] = 0.0f;
#pragma unroll
            for (int j = 0; j < 2; j++) {
                uint32_t kb0 = (f * 8 + qr) * QS + j * 8 + lm;
                mma_bf16(S[f], aQh[j][0], aQh[j][1], aQh[j][2], aQh[j][3],
                         kh[kb0], kh[kb0 + 4]);
            }
        }
#pragma unroll
        for (int f = 0; f < 8; f++) {
            rs0 += fast_exp2(S[f][0] * SC) + fast_exp2(S[f][1] * SC);
            rs1 += fast_exp2(S[f][2] * SC) + fast_exp2(S[f][3] * SC);
        }
    }

    rs0 += __shfl_xor_sync(0xFFFFFFFFu, rs0, 1);
    rs0 += __shfl_xor_sync(0xFFFFFFFFu, rs0, 2);
    rs1 += __shfl_xor_sync(0xFFFFFFFFu, rs1, 1);
    rs1 += __shfl_xor_sync(0xFFFFFFFFu, rs1, 2);
    const float li0 = -__log2f(rs0);
    const float li1 = -__log2f(rs1);

    // ================= Loop B: normalized scores + PV =================
    float O[4][4];
#pragma unroll
    for (int g = 0; g < 4; g++)
#pragma unroll
        for (int i = 0; i < 4; i++) O[g][i] = 0.0f;

    float* srow0 = scores + ((size_t)((h * NB + n) * TLEN + qb * 128 + m0w + qr)) * TLEN;
    float* srow1 = srow0 + 8 * (size_t)TLEN;

    __syncthreads();   // loop A fully done before restaging buf0
    issueKh(0, sb + OFF_K);
    issueKl(0, sb + OFF_K);
    issueVT(0, sb + OFF_VT);
    CP_COMMIT;

    for (int tile = 0; tile < 32; tile++) {
        const int kb = tile * 64;
        const int cur = tile & 1;
        CP_WAIT0;
        __syncthreads();
        if (tile + 1 < 32) {
            issueKh((tile + 1) * 64, sb + OFF_K + (cur ^ 1) * 10240);
            issueKl((tile + 1) * 64, sb + OFF_K + (cur ^ 1) * 10240);
            issueVT(tile + 1, sb + OFF_VT + (cur ^ 1) * 9216);
            CP_COMMIT;
        }
        const uint32_t* kh = (const uint32_t*)(smem + OFF_K + cur * 10240);
        const uint32_t* kl = kh + 1280;
        const uint32_t* sVTh = (const uint32_t*)(smem + OFF_VT + cur * 9216);
        const uint32_t* sVTl = sVTh + 1152;

        // ---- QK^T: 3-term split
        float S[8][4];
#pragma unroll
        for (int f = 0; f < 8; f++) {
#pragma unroll
            for (int i = 0; i < 4; i++) S[f][i] = 0.0f;
#pragma unroll
            for (int j = 0; j < 2; j++) {
                uint32_t kb0 = (f * 8 + qr) * QS + j * 8 + lm;
                uint32_t kh0 = kh[kb0], kh1 = kh[kb0 + 4];
                uint32_t kl0 = kl[kb0], kl1 = kl[kb0 + 4];
                mma_bf16(S[f], aQh[j][0], aQh[j][1], aQh[j][2], aQh[j][3], kh0, kh1);
                mma_bf16(S[f], aQh[j][0], aQh[j][1], aQh[j][2], aQh[j][3], kl0, kl1);
                mma_bf16(S[f], aQl[j][0], aQl[j][1], aQl[j][2], aQl[j][3], kh0, kh1);
            }
        }

        // ---- normalized exp + final score store
#pragma unroll
        for (int f = 0; f < 8; f++) {
            float p0 = fast_exp2(fmaf(S[f][0], SC, li0));
            float p1 = fast_exp2(fmaf(S[f][1], SC, li0));
            float p2 = fast_exp2(fmaf(S[f][2], SC, li1));
            float p3 = fast_exp2(fmaf(S[f][3], SC, li1));
            S[f][0] = p0; S[f][1] = p1; S[f][2] = p2; S[f][3] = p3;
            const int col = kb + f * 8 + lm * 2;
            __stcs((float2*)(srow0 + col), make_float2(p0, p1));
            __stcs((float2*)(srow1 + col), make_float2(p2, p3));
        }

        // ---- PV: 3-term split (PhVh + PhVl + PlVh)
#pragma unroll
        for (int kk = 0; kk < 4; kk++) {
            uint32_t ah[4], al[4];
            split2(S[2 * kk][0],     S[2 * kk][1],     ah[0], al[0]);
            split2(S[2 * kk][2],     S[2 * kk][3],     ah[1], al[1]);
            split2(S[2 * kk + 1][0], S[2 * kk + 1][1], ah[2], al[2]);
            split2(S[2 * kk + 1][2], S[2 * kk + 1][3], ah[3], al[3]);
#pragma unroll
            for (int g = 0; g < 4; g++) {
                uint32_t vb = (g * 8 + qr) * VS + kk * 8 + lm;
                uint32_t vh0 = sVTh[vb], vh1 = sVTh[vb + 4];
                uint32_t vl0 = sVTl[vb], vl1 = sVTl[vb + 4];
                mma_bf16(O[g], ah[0], ah[1], ah[2], ah[3], vh0, vh1);
                mma_bf16(O[g], ah[0], ah[1], ah[2], ah[3], vl0, vl1);
                mma_bf16(O[g], al[0], al[1], al[2], al[3], vh0, vh1);
            }
        }
    }

    // ---- O write (already normalized): [n, T, h*32 + dv]
    float* Og0 = g_O + ((size_t)(n * TLEN + qb * 128 + m0w + qr)) * DM + h * DK;
    float* Og1 = Og0 + 8 * (size_t)DM;
#pragma unroll
    for (int g = 0; g < 4; g++) {
        const int col = g * 8 + lm * 2;
        *(float2*)(Og0 + col) = make_float2(O[g][0], O[g][1]);
        *(float2*)(Og1 + col) = make_float2(O[g][2], O[g][3]);
    }
}

// ---------------- launcher ----------------
extern "C" void kernel_launch(void* const* d_in, const int* in_sizes, int n_in,
                              void* d_out, int out_size) {
    (void)in_sizes; (void)n_in; (void)out_size;
    const float* query = (const float*)d_in[0];
    const float* key   = (const float*)d_in[1];
    const float* Wq    = (const float*)d_in[2];
    const float* Wk    = (const float*)d_in[3];
    const float* Wv    = (const float*)d_in[4];
    const float* Wo    = (const float*)d_in[5];

    float* out    = (float*)d_out;                      // [4, 2048, 256]
    float* scores = (float*)d_out + (size_t)ROWS * DM;  // [8, 4, 2048, 2048]

    uint32_t *pqh, *pql, *pkh, *pkl, *pvh, *pvl, *pwth, *pwtl;
    float* pO;
    cudaGetSymbolAddress((void**)&pqh, g_qh);
    cudaGetSymbolAddress((void**)&pql, g_ql);
    cudaGetSymbolAddress((void**)&pkh, g_kh);
    cudaGetSymbolAddress((void**)&pkl, g_kl);
    cudaGetSymbolAddress((void**)&pvh, g_vh);
    cudaGetSymbolAddress((void**)&pvl, g_vl);
    cudaGetSymbolAddress((void**)&pwth, g_wth);
    cudaGetSymbolAddress((void**)&pwtl, g_wtl);
    cudaGetSymbolAddress((void**)&pO, g_O);

    static bool attr_set = false;
    if (!attr_set) {
        cudaFuncSetAttribute(attn_mma, cudaFuncAttributeMaxDynamicSharedMemorySize,
                             ATTN_SMEM);
        attr_set = true;
    }

    prep_w<<<512, 256>>>(Wq, Wk, Wv, Wo);

    dim3 gg(ROWS / 128, DM / 64);   // (64, 4)
    gemm_tc<true><<<gg, 256>>>(query, pwth,             pwtl,             pqh, pql, nullptr);
    gemm_tc<true><<<gg, 256>>>(query, pwth + 1 * 32768, pwtl + 1 * 32768, pkh, pkl, nullptr);
    gemm_tc<true><<<gg, 256>>>(key,   pwth + 2 * 32768, pwtl + 2 * 32768, pvh, pvl, nullptr);

    dim3 vg(TLEN / 64, NB, NH);     // (32, 4, 8)
    vtrans<<<vg, 256>>>();

    dim3 attnGrid(TLEN / 128, NB, NH);   // (16, 4, 8)
    attn_mma<<<attnGrid, 256, ATTN_SMEM>>>(scores);

    gemm_tc<false><<<gg, 256>>>(pO, pwth + 3 * 32768, pwtl + 3 * 32768,
                                nullptr, nullptr, out);
}